// round 2
// baseline (speedup 1.0000x reference)
#include <cuda_runtime.h>
#include <math_constants.h>

#define B_ 1024
#define D_ 512
#define O_ 256
#define NSPLIT 8   // B-splits for phase-1 partials

// ---- scratch (no allocations allowed) ----
__device__ float g_Mpart[NSPLIT * D_ * O_]; // phase-1 partial sums (4 MB)
__device__ float g_relx[D_ * O_];
__device__ float g_relw[B_ * O_];
__device__ float g_Sx[D_];
__device__ float g_Sw[O_];
__device__ float g_pm[D_ * O_];             // prefix-min of w down each column
__device__ int   g_argw[O_];                // first argmin_d w[:,o]

// ============================================================
// k_pre: Sx[d] (fp32, unchanged), Sw[o] (fp64 for accuracy),
//        prefix-min(w) + first-argmin(w) per column
// ============================================================
__global__ __launch_bounds__(256) void k_pre(const float* __restrict__ x,
                                             const float* __restrict__ w) {
    __shared__ float sm[256];
    __shared__ double smd[256];
    int blk = blockIdx.x;
    int t = threadIdx.x;
    if (blk < D_) {                       // Sx[d] = sum_b (1-x[b,d])  (unchanged)
        int d = blk;
        float s = 0.0f;
        for (int b = t; b < B_; b += 256) s += (1.0f - x[b * D_ + d]);
        sm[t] = s; __syncthreads();
        for (int k = 128; k > 0; k >>= 1) {
            if (t < k) sm[t] += sm[t + k];
            __syncthreads();
        }
        if (t == 0) g_Sx[d] = sm[0];
    } else if (blk < D_ + O_) {           // Sw[o] = sum_d (1-w[d,o])  (fp64)
        int o = blk - D_;
        double s = 0.0;
        for (int d = t; d < D_; d += 256) s += (double)(1.0f - w[d * O_ + o]);
        smd[t] = s; __syncthreads();
        for (int k = 128; k > 0; k >>= 1) {
            if (t < k) smd[t] += smd[t + k];
            __syncthreads();
        }
        if (t == 0) g_Sw[o] = (float)smd[0];
    } else {                              // one block: prefix-min + argmin per o
        int o = t;                        // 256 threads == O_
        float pm = CUDART_INF_F;
        float best = CUDART_INF_F;
        int bi = 0;
        for (int d = 0; d < D_; ++d) {
            float wv = w[d * O_ + o];
            pm = fminf(pm, wv);
            g_pm[d * O_ + o] = pm;
            if (wv < best) { best = wv; bi = d; }   // strict < => first index
        }
        g_argw[o] = bi;
    }
}

// ============================================================
// k1: partial M[d,o] = sum_b min(1-x[b,d], 1-t[b,o]) over a B-split
// (UNCHANGED from R1 — output 0 was bit-exact with this path)
// ============================================================
__global__ __launch_bounds__(256) void k1(const float* __restrict__ x,
                                          const float* __restrict__ tt) {
    const int d0 = blockIdx.x * 32;
    const int o0 = blockIdx.y * 64;
    const int b0 = blockIdx.z * (B_ / NSPLIT);
    __shared__ float xs[32][32];   // [bb][dd]
    __shared__ float ts[32][64];   // [bb][oo]
    const int tid = threadIdx.x;
    const int dg = tid & 15;       // -> 2 d's
    const int og = tid >> 4;       // -> 4 o's

    float acc[2][4];
#pragma unroll
    for (int i = 0; i < 2; i++)
#pragma unroll
        for (int j = 0; j < 4; j++) acc[i][j] = 0.0f;

    for (int bc = 0; bc < B_ / NSPLIT; bc += 32) {
#pragma unroll
        for (int i = tid; i < 32 * 32; i += 256) {
            int bb = i >> 5, dd = i & 31;
            xs[bb][dd] = 1.0f - x[(b0 + bc + bb) * D_ + d0 + dd];
        }
#pragma unroll
        for (int i = tid; i < 32 * 64; i += 256) {
            int bb = i >> 6, oo = i & 63;
            ts[bb][oo] = 1.0f - tt[(b0 + bc + bb) * O_ + o0 + oo];
        }
        __syncthreads();
#pragma unroll 4
        for (int bb = 0; bb < 32; ++bb) {
            float x0 = xs[bb][dg * 2 + 0];
            float x1 = xs[bb][dg * 2 + 1];
            float t0 = ts[bb][og * 4 + 0];
            float t1 = ts[bb][og * 4 + 1];
            float t2 = ts[bb][og * 4 + 2];
            float t3 = ts[bb][og * 4 + 3];
            acc[0][0] += fminf(x0, t0); acc[0][1] += fminf(x0, t1);
            acc[0][2] += fminf(x0, t2); acc[0][3] += fminf(x0, t3);
            acc[1][0] += fminf(x1, t0); acc[1][1] += fminf(x1, t1);
            acc[1][2] += fminf(x1, t2); acc[1][3] += fminf(x1, t3);
        }
        __syncthreads();
    }
    float* outp = g_Mpart + blockIdx.z * (D_ * O_);
#pragma unroll
    for (int i = 0; i < 2; i++)
#pragma unroll
        for (int j = 0; j < 4; j++)
            outp[(d0 + dg * 2 + i) * O_ + (o0 + og * 4 + j)] = acc[i][j];
}

// k1b: combine splits (fixed order), compute rel_x  (UNCHANGED)
__global__ __launch_bounds__(256) void k1b() {
    int idx = blockIdx.x * 256 + threadIdx.x;   // D_*O_ threads
    int d = idx >> 8;                           // idx / O_
    float s = 0.0f;
#pragma unroll
    for (int z = 0; z < NSPLIT; z++) s += g_Mpart[z * (D_ * O_) + idx];
    g_relx[idx] = 1.0f - __fdiv_rn(s, g_Sx[d]);
}

// ============================================================
// k2: rel_w[b,o] = 1 - (sum_d min(1-w[d,o], 1-t[b,o])) / Sw[o]
// NOW with Kahan-compensated fp32 accumulation (__fadd_rn: fast-math-proof)
// ============================================================
__device__ __forceinline__ void kahan_add(float v, float& acc, float& comp) {
    float y  = __fadd_rn(v, -comp);
    float t2 = __fadd_rn(acc, y);
    comp     = __fadd_rn(__fadd_rn(t2, -acc), -y);
    acc      = t2;
}

__global__ __launch_bounds__(256) void k2(const float* __restrict__ w,
                                          const float* __restrict__ tt) {
    const int o0 = blockIdx.x * 32;
    const int b0 = blockIdx.y * 32;
    __shared__ float ws[64][32];   // [dd][oo]
    const int tid = threadIdx.x;
    const int og = tid & 15;       // -> 2 o's
    const int bg = tid >> 4;       // -> 2 b's

    float tc[2][2], acc[2][2], cmp[2][2];
#pragma unroll
    for (int i = 0; i < 2; i++)
#pragma unroll
        for (int j = 0; j < 2; j++) {
            tc[i][j] = 1.0f - tt[(b0 + bg * 2 + i) * O_ + (o0 + og * 2 + j)];
            acc[i][j] = 0.0f;
            cmp[i][j] = 0.0f;
        }

    for (int dc = 0; dc < D_; dc += 64) {
#pragma unroll
        for (int i = tid; i < 64 * 32; i += 256) {
            int dd = i >> 5, oo = i & 31;
            ws[dd][oo] = 1.0f - w[(dc + dd) * O_ + o0 + oo];
        }
        __syncthreads();
#pragma unroll 4
        for (int dd = 0; dd < 64; ++dd) {
            float w0 = ws[dd][og * 2 + 0];
            float w1 = ws[dd][og * 2 + 1];
            kahan_add(fminf(w0, tc[0][0]), acc[0][0], cmp[0][0]);
            kahan_add(fminf(w1, tc[0][1]), acc[0][1], cmp[0][1]);
            kahan_add(fminf(w0, tc[1][0]), acc[1][0], cmp[1][0]);
            kahan_add(fminf(w1, tc[1][1]), acc[1][1], cmp[1][1]);
        }
        __syncthreads();
    }
#pragma unroll
    for (int i = 0; i < 2; i++)
#pragma unroll
        for (int j = 0; j < 2; j++) {
            int o = o0 + og * 2 + j;
            g_relw[(b0 + bg * 2 + i) * O_ + o] = 1.0f - __fdiv_rn(acc[i][j], g_Sw[o]);
        }
}

// ============================================================
// k3: ind_x = argmin_d max(x[b,d], rel_x[d,o]); out = max(x[b,d*], w[d*,o])
// (UNCHANGED)
// ============================================================
__global__ __launch_bounds__(256) void k3(const float* __restrict__ x,
                                          const float* __restrict__ w,
                                          float* __restrict__ out) {
    const int o0 = blockIdx.x * 16;
    const int b0 = blockIdx.y * 16;
    __shared__ float xsh[16][129];   // padded: stride 129 kills 2-way conflicts
    __shared__ float rsh[128][16];
    const int tid = threadIdx.x;
    const int ol = tid & 15;
    const int bl = tid >> 4;

    float best = CUDART_INF_F;
    int bidx = 0;

    for (int dc = 0; dc < D_; dc += 128) {
#pragma unroll
        for (int i = tid; i < 16 * 128; i += 256) {
            int row = i >> 7, col = i & 127;
            xsh[row][col] = x[(b0 + row) * D_ + dc + col];
        }
#pragma unroll
        for (int i = tid; i < 128 * 16; i += 256) {
            int row = i >> 4, col = i & 15;
            rsh[row][col] = g_relx[(dc + row) * O_ + o0 + col];
        }
        __syncthreads();
#pragma unroll 4
        for (int dd = 0; dd < 128; ++dd) {
            float v = fmaxf(xsh[bl][dd], rsh[dd][ol]);
            if (v < best) { best = v; bidx = dc + dd; }   // strict < => first index
        }
        __syncthreads();
    }
    int b = b0 + bl, o = o0 + ol;
    out[b * O_ + o] = fmaxf(x[b * D_ + bidx], w[bidx * O_ + o]);
}

// ============================================================
// k4: ind_w via exact shortcut (UNCHANGED):
//   d* = first d with w[d,o] <= rel_w[b,o]  (binary search on prefix-min)
//        else first argmin_d w[d,o]
//   out = max(x[b,d*], w[d*,o])
// ============================================================
__global__ __launch_bounds__(256) void k4(const float* __restrict__ x,
                                          const float* __restrict__ w,
                                          float* __restrict__ out) {
    int idx = blockIdx.x * 256 + threadIdx.x;   // B_*O_ threads
    int b = idx >> 8;                            // / O_
    int o = idx & 255;
    float c = g_relw[idx];
    int lo = 0, hi = D_;
    while (lo < hi) {                            // first d with pm[d] <= c
        int mid = (lo + hi) >> 1;
        if (g_pm[mid * O_ + o] <= c) hi = mid; else lo = mid + 1;
    }
    int dstar = (lo < D_) ? lo : g_argw[o];
    out[idx] = fmaxf(x[b * D_ + dstar], w[dstar * O_ + o]);
}

// ============================================================
extern "C" void kernel_launch(void* const* d_in, const int* in_sizes, int n_in,
                              void* d_out, int out_size) {
    const float* x = (const float*)d_in[0];   // (B, D)
    const float* w = (const float*)d_in[1];   // (D, O)
    const float* t = (const float*)d_in[2];   // (B, O)
    float* out = (float*)d_out;               // [chosen_x (B,O); chosen_w (B,O)]

    k_pre<<<D_ + O_ + 1, 256>>>(x, w);
    k1<<<dim3(D_ / 32, O_ / 64, NSPLIT), 256>>>(x, t);
    k1b<<<(D_ * O_) / 256, 256>>>();
    k2<<<dim3(O_ / 32, B_ / 32), 256>>>(w, t);
    k3<<<dim3(O_ / 16, B_ / 16), 256>>>(x, w, out);
    k4<<<(B_ * O_) / 256, 256>>>(x, w, out + B_ * O_);
}

// round 4
// speedup vs baseline: 1.7358x; 1.7358x over previous
#include <cuda_runtime.h>
#include <math_constants.h>
#include <cstdint>

#define B_ 1024
#define D_ 512
#define O_ 256
#define NSPLIT 8

// ---- scratch (no allocations allowed) ----
__device__ float  g_Mpart[NSPLIT * D_ * O_]; // phase-1 partial sums
__device__ float  g_relx[D_ * O_];
__device__ float  g_relw[B_ * O_];
__device__ float  g_Sx[D_];
__device__ float  g_Sw[O_];
__device__ float  g_pm[D_ * O_];             // prefix-min of w down each column
__device__ int    g_argw[O_];                // first argmin_d w[:,o]
__device__ float  g_xT[D_ * B_];             // x transposed [d][b]
__device__ float  g_sw[O_ * D_];             // sorted (1-w) ascending, per o
__device__ double g_pref[O_ * D_];           // fp64 inclusive prefix of g_sw
__device__ float  g_srel[O_ * D_];           // sorted rel_x per o (ascending)
__device__ int    g_sidx[O_ * D_];           // original d for g_srel

// ============================================================
// kA: fused preprocessing
//   blocks [0,512):    Sx[d] (UNCHANGED math from R2 — output-0 chain)
//   blocks [512,768):  per-o: prefix-min(w)+argw, sort(1-w), fp64 prefix, Sw
//   blocks [768,1280): transpose x -> g_xT
// ============================================================
__global__ __launch_bounds__(256) void kA(const float* __restrict__ x,
                                          const float* __restrict__ w) {
    __shared__ float sm[256];
    __shared__ float s0[512];   // original w column
    __shared__ float s1[512];   // scan ping / sort array
    __shared__ float s2[512];   // scan pong
    __shared__ double d0[512];
    __shared__ double d1[512];
    __shared__ int s_argw;
    __shared__ float tile[32][33];

    const int blk = blockIdx.x;
    const int t = threadIdx.x;

    if (blk < D_) {
        // ---- Sx[d] = sum_b (1-x[b,d])  (identical to R2) ----
        int d = blk;
        float s = 0.0f;
        for (int b = t; b < B_; b += 256) s += (1.0f - x[b * D_ + d]);
        sm[t] = s; __syncthreads();
        for (int k = 128; k > 0; k >>= 1) {
            if (t < k) sm[t] += sm[t + k];
            __syncthreads();
        }
        if (t == 0) g_Sx[d] = sm[0];
    } else if (blk < D_ + O_) {
        const int o = blk - D_;
        // load original w column
        s0[t] = w[t * O_ + o];
        s0[t + 256] = w[(t + 256) * O_ + o];
        if (t == 0) s_argw = 0x7FFFFFFF;
        // ---- prefix-min scan (inclusive) ----
        s1[t] = s0[t]; s1[t + 256] = s0[t + 256];
        {
            float* src = s1; float* dst = s2;
            for (int off = 1; off < D_; off <<= 1) {
                __syncthreads();
                for (int e = t; e < D_; e += 256) {
                    float v = src[e];
                    if (e >= off) v = fminf(v, src[e - off]);
                    dst[e] = v;
                }
                float* tmp = src; src = dst; dst = tmp;
            }
            __syncthreads();
            for (int e = t; e < D_; e += 256) g_pm[e * O_ + o] = src[e];
            float wmin = src[D_ - 1];
            __syncthreads();
            for (int e = t; e < D_; e += 256)
                if (s0[e] == wmin) atomicMin(&s_argw, e);
            __syncthreads();
            if (t == 0) g_argw[o] = s_argw;
        }
        // ---- sort a' = 1 - w ascending (bitonic, n=512) ----
        __syncthreads();
        s1[t] = 1.0f - s0[t];
        s1[t + 256] = 1.0f - s0[t + 256];
        for (int k = 2; k <= D_; k <<= 1) {
            for (int j = k >> 1; j > 0; j >>= 1) {
                __syncthreads();
                for (int e = t; e < D_; e += 256) {
                    int p = e ^ j;
                    if (p > e) {
                        bool up = ((e & k) == 0);
                        float a = s1[e], b2 = s1[p];
                        if (up ? (a > b2) : (a < b2)) { s1[e] = b2; s1[p] = a; }
                    }
                }
            }
        }
        __syncthreads();
        g_sw[o * D_ + t] = s1[t];
        g_sw[o * D_ + t + 256] = s1[t + 256];
        // ---- fp64 inclusive prefix (exact) ----
        d0[t] = (double)s1[t]; d0[t + 256] = (double)s1[t + 256];
        {
            double* src = d0; double* dst = d1;
            for (int off = 1; off < D_; off <<= 1) {
                __syncthreads();
                for (int e = t; e < D_; e += 256) {
                    double v = src[e];
                    if (e >= off) v += src[e - off];
                    dst[e] = v;
                }
                double* tmp = src; src = dst; dst = tmp;
            }
            __syncthreads();
            for (int e = t; e < D_; e += 256) g_pref[o * D_ + e] = src[e];
            if (t == 0) g_Sw[o] = (float)src[D_ - 1];
        }
    } else {
        // ---- transpose x [B,D] -> g_xT [D,B], 32x32 tiles ----
        const int tix = blk - (D_ + O_);
        const int tx = tix & 15;            // d tile (D/32 = 16)
        const int ty = tix >> 4;            // b tile (B/32 = 32)
        const int d0i = tx * 32, b0i = ty * 32;
        const int col = t & 31, rr = t >> 5;   // rr in 0..7
#pragma unroll
        for (int i = 0; i < 4; i++) {
            int row = rr + 8 * i;
            tile[row][col] = x[(b0i + row) * D_ + d0i + col];
        }
        __syncthreads();
#pragma unroll
        for (int i = 0; i < 4; i++) {
            int row = rr + 8 * i;
            g_xT[(d0i + row) * B_ + b0i + col] = tile[col][row];
        }
    }
}

// ============================================================
// k1: partial M[d,o] = sum_b min(1-x[b,d], 1-t[b,o])  (UNCHANGED)
// ============================================================
__global__ __launch_bounds__(256) void k1(const float* __restrict__ x,
                                          const float* __restrict__ tt) {
    const int d0 = blockIdx.x * 32;
    const int o0 = blockIdx.y * 64;
    const int b0 = blockIdx.z * (B_ / NSPLIT);
    __shared__ float xs[32][32];
    __shared__ float ts[32][64];
    const int tid = threadIdx.x;
    const int dg = tid & 15;
    const int og = tid >> 4;

    float acc[2][4];
#pragma unroll
    for (int i = 0; i < 2; i++)
#pragma unroll
        for (int j = 0; j < 4; j++) acc[i][j] = 0.0f;

    for (int bc = 0; bc < B_ / NSPLIT; bc += 32) {
#pragma unroll
        for (int i = tid; i < 32 * 32; i += 256) {
            int bb = i >> 5, dd = i & 31;
            xs[bb][dd] = 1.0f - x[(b0 + bc + bb) * D_ + d0 + dd];
        }
#pragma unroll
        for (int i = tid; i < 32 * 64; i += 256) {
            int bb = i >> 6, oo = i & 63;
            ts[bb][oo] = 1.0f - tt[(b0 + bc + bb) * O_ + o0 + oo];
        }
        __syncthreads();
#pragma unroll 4
        for (int bb = 0; bb < 32; ++bb) {
            float x0 = xs[bb][dg * 2 + 0];
            float x1 = xs[bb][dg * 2 + 1];
            float t0 = ts[bb][og * 4 + 0];
            float t1 = ts[bb][og * 4 + 1];
            float t2 = ts[bb][og * 4 + 2];
            float t3 = ts[bb][og * 4 + 3];
            acc[0][0] += fminf(x0, t0); acc[0][1] += fminf(x0, t1);
            acc[0][2] += fminf(x0, t2); acc[0][3] += fminf(x0, t3);
            acc[1][0] += fminf(x1, t0); acc[1][1] += fminf(x1, t1);
            acc[1][2] += fminf(x1, t2); acc[1][3] += fminf(x1, t3);
        }
        __syncthreads();
    }
    float* outp = g_Mpart + blockIdx.z * (D_ * O_);
#pragma unroll
    for (int i = 0; i < 2; i++)
#pragma unroll
        for (int j = 0; j < 4; j++)
            outp[(d0 + dg * 2 + i) * O_ + (o0 + og * 4 + j)] = acc[i][j];
}

// k1b: combine splits (fixed order), compute rel_x  (UNCHANGED)
__global__ __launch_bounds__(256) void k1b() {
    int idx = blockIdx.x * 256 + threadIdx.x;
    int d = idx >> 8;
    float s = 0.0f;
#pragma unroll
    for (int z = 0; z < NSPLIT; z++) s += g_Mpart[z * (D_ * O_) + idx];
    g_relx[idx] = 1.0f - __fdiv_rn(s, g_Sx[d]);
}

// ============================================================
// kB: fused
//   blocks [0,256):    sort rel_x[:,o] ascending with original indices
//   blocks [256,1280): rel_w via binary search over sorted (1-w) + fp64 prefix
// ============================================================
__global__ __launch_bounds__(256) void kB(const float* __restrict__ tt) {
    __shared__ float sv[512];
    __shared__ int   si[512];
    __shared__ float sa[512];
    __shared__ double sP[512];

    const int blk = blockIdx.x;
    const int t = threadIdx.x;

    if (blk < O_) {
        const int o = blk;
        sv[t] = g_relx[t * O_ + o];          si[t] = t;
        sv[t + 256] = g_relx[(t + 256) * O_ + o]; si[t + 256] = t + 256;
        for (int k = 2; k <= D_; k <<= 1) {
            for (int j = k >> 1; j > 0; j >>= 1) {
                __syncthreads();
                for (int e = t; e < D_; e += 256) {
                    int p = e ^ j;
                    if (p > e) {
                        bool up = ((e & k) == 0);
                        float a = sv[e], b2 = sv[p];
                        if (up ? (a > b2) : (a < b2)) {
                            sv[e] = b2; sv[p] = a;
                            int ti = si[e]; si[e] = si[p]; si[p] = ti;
                        }
                    }
                }
            }
        }
        __syncthreads();
        g_srel[o * D_ + t] = sv[t];       g_sidx[o * D_ + t] = si[t];
        g_srel[o * D_ + t + 256] = sv[t + 256]; g_sidx[o * D_ + t + 256] = si[t + 256];
    } else {
        const int q = blk - O_;
        const int o = q & (O_ - 1);
        const int b0 = (q >> 8) * 256;
        sa[t] = g_sw[o * D_ + t];       sa[t + 256] = g_sw[o * D_ + t + 256];
        sP[t] = g_pref[o * D_ + t];     sP[t + 256] = g_pref[o * D_ + t + 256];
        const float sw = g_Sw[o];
        __syncthreads();
        const int b = b0 + t;
        const float c = 1.0f - tt[b * O_ + o];
        int lo = 0, hi = D_;
        while (lo < hi) {                       // j = count(a' <= c)
            int mid = (lo + hi) >> 1;
            if (sa[mid] <= c) lo = mid + 1; else hi = mid;
        }
        const int j = lo;
        double S = (j > 0 ? sP[j - 1] : 0.0) + (double)c * (double)(D_ - j);
        g_relw[b * O_ + o] = 1.0f - __fdiv_rn((float)S, sw);
    }
}

// ============================================================
// kC: fused
//   blocks [0,1024):    k3: argmin_d max(x,rel_x) via sorted-scan early exit
//   blocks [1024,2048): k4: argmin_d max(rel_w,w) via prefix-min binary search
// ============================================================
__global__ __launch_bounds__(256) void kC(const float* __restrict__ x,
                                          const float* __restrict__ w,
                                          float* __restrict__ out) {
    __shared__ float sr[512];
    __shared__ int   sd[512];

    const int blk = blockIdx.x;
    const int t = threadIdx.x;

    if (blk < 1024) {
        const int o = blk & (O_ - 1);
        const int b0 = (blk >> 8) * 256;
        sr[t] = g_srel[o * D_ + t];       sd[t] = g_sidx[o * D_ + t];
        sr[t + 256] = g_srel[o * D_ + t + 256]; sd[t + 256] = g_sidx[o * D_ + t + 256];
        __syncthreads();
        const int b = b0 + t;
        float best = CUDART_INF_F;
        int bestd = 0x7FFFFFFF;
        for (int k = 0; k < D_; ++k) {
            float r = sr[k];
            if (r > best) break;            // all later have max >= r > best
            int d = sd[k];
            float xv = g_xT[d * B_ + b];
            float v = fmaxf(xv, r);
            if (v < best || (v == best && d < bestd)) { best = v; bestd = d; }
        }
        out[b * O_ + o] = fmaxf(g_xT[bestd * B_ + b], w[bestd * O_ + o]);
    } else {
        const int idx = (blk - 1024) * 256 + t;
        const int b = idx >> 8;
        const int o = idx & 255;
        const float c = g_relw[idx];
        int lo = 0, hi = D_;
        while (lo < hi) {                   // first d with pm[d] <= c
            int mid = (lo + hi) >> 1;
            if (g_pm[mid * O_ + o] <= c) hi = mid; else lo = mid + 1;
        }
        const int dstar = (lo < D_) ? lo : g_argw[o];
        out[B_ * O_ + idx] = fmaxf(x[b * D_ + dstar], w[dstar * O_ + o]);
    }
}

// ============================================================
extern "C" void kernel_launch(void* const* d_in, const int* in_sizes, int n_in,
                              void* d_out, int out_size) {
    const float* x = (const float*)d_in[0];   // (B, D)
    const float* w = (const float*)d_in[1];   // (D, O)
    const float* t = (const float*)d_in[2];   // (B, O)
    float* out = (float*)d_out;               // [chosen_x (B,O); chosen_w (B,O)]

    kA<<<D_ + O_ + 512, 256>>>(x, w);
    k1<<<dim3(D_ / 32, O_ / 64, NSPLIT), 256>>>(x, t);
    k1b<<<(D_ * O_) / 256, 256>>>();
    kB<<<O_ + 1024, 256>>>(t);
    kC<<<2048, 256>>>(x, w, out);
}

// round 5
// speedup vs baseline: 1.9672x; 1.1333x over previous
#include <cuda_runtime.h>
#include <math_constants.h>

#define B_ 1024
#define D_ 512
#define O_ 256
#define NSPLIT 8

// ---- scratch (no allocations allowed) ----
__device__ float  g_Mpart[NSPLIT * D_ * O_]; // phase-1 partial sums
__device__ float  g_relx[D_ * O_];
__device__ float  g_relw[B_ * O_];
__device__ float  g_Sx[D_];
__device__ float  g_pm[D_ * O_];             // prefix-min of w down each column
__device__ int    g_argw[O_];                // first argmin_d w[:,o]
__device__ float  g_xT[D_ * B_];             // x transposed [d][b]
__device__ float  g_wval[O_ * D_];           // bucket-ordered a'=1-w per o
__device__ int    g_wbs[O_ * 260];           // bucket starts (257 used) per o
__device__ double g_wbp[O_ * 256];           // fp64 inclusive prefix of bucket sums

// ============================================================
// kP: blocks [0,512) k1-partials | [512,1024) Sx | [1024,1280) w-bucketing
//     | [1280,1792) transpose x
// ============================================================
__global__ __launch_bounds__(256) void kP(const float* __restrict__ x,
                                          const float* __restrict__ w) {
    __shared__ __align__(16) unsigned char raw[16384];
    __shared__ int s_argw;
    const int blk = blockIdx.x;
    const int t = threadIdx.x;

    if (blk < 512) {
        // ---- k1: partial M[d,o] = sum_b min(1-x,1-t') — IDENTICAL math ----
        // (uses tt passed via w? no — k1 needs t; handled in kP2) — placeholder
    } else if (blk < 1024) {
        // ---- Sx[d] = sum_b (1-x[b,d]) (identical to R2) ----
        float* sm = (float*)raw;
        int d = blk - 512;
        float s = 0.0f;
        for (int b = t; b < B_; b += 256) s += (1.0f - x[b * D_ + d]);
        sm[t] = s; __syncthreads();
        for (int k = 128; k > 0; k >>= 1) {
            if (t < k) sm[t] += sm[t + k];
            __syncthreads();
        }
        if (t == 0) g_Sx[d] = sm[0];
    } else if (blk < 1280) {
        // ---- per-o: prefix-min(w)+argw, bucket (1-w), fp64 bucket prefix ----
        const int o = blk - 1024;
        float*  F0 = (float*)raw;            // 512: w column
        float*  F1 = (float*)(raw + 2048);   // 512: scan ping
        float*  F2 = (float*)(raw + 4096);   // 512: scan pong
        int*    KY = (int*)(raw + 6144);     // 512: keys
        int*    H0 = (int*)(raw + 8192);     // 256
        int*    H1 = (int*)(raw + 9216);     // 256
        double* P0 = (double*)(raw + 10240); // 256
        double* P1 = (double*)(raw + 12288); // 256

        F0[t] = w[t * O_ + o];
        F0[t + 256] = w[(t + 256) * O_ + o];
        if (t == 0) s_argw = 0x7FFFFFFF;
        F1[t] = F0[t]; F1[t + 256] = F0[t + 256];
        {   // inclusive prefix-min
            float* src = F1; float* dst = F2;
            for (int off = 1; off < D_; off <<= 1) {
                __syncthreads();
                for (int e = t; e < D_; e += 256) {
                    float v = src[e];
                    if (e >= off) v = fminf(v, src[e - off]);
                    dst[e] = v;
                }
                float* tmp = src; src = dst; dst = tmp;
            }
            __syncthreads();
            for (int e = t; e < D_; e += 256) g_pm[e * O_ + o] = src[e];
            float wmin = src[D_ - 1];
            __syncthreads();
            for (int e = t; e < D_; e += 256)
                if (F0[e] == wmin) atomicMin(&s_argw, e);
        }
        // keys & histogram of a' = 1-w
        H0[t] = 0;
        __syncthreads();
        for (int e = t; e < D_; e += 256) {
            float a = 1.0f - F0[e];
            int k = (int)(a * 256.0f); k = max(0, min(255, k));
            KY[e] = k;
            atomicAdd(&H0[k], 1);
        }
        __syncthreads();
        if (t == 0) g_argw[o] = s_argw;
        // inclusive int scan over 256 bins
        int* isrc = H0; int* idst = H1;
        for (int off = 1; off < 256; off <<= 1) {
            __syncthreads();
            int v = isrc[t]; if (t >= off) v += isrc[t - off];
            idst[t] = v;
            int* tmp = isrc; isrc = idst; idst = tmp;
        }
        __syncthreads();
        int excl = (t == 0) ? 0 : isrc[t - 1];
        g_wbs[o * 260 + t] = excl;
        if (t == 255) g_wbs[o * 260 + 256] = D_;
        idst[t] = excl;           // running offsets
        P0[t] = 0.0;
        __syncthreads();
        // scatter + fp64 bucket sums
        for (int e = t; e < D_; e += 256) {
            float a = 1.0f - F0[e];
            int k = KY[e];
            int pos = atomicAdd(&idst[k], 1);
            g_wval[o * D_ + pos] = a;
            atomicAdd(&P0[k], (double)a);
        }
        // fp64 inclusive prefix over buckets
        double* dsrc = P0; double* ddst = P1;
        for (int off = 1; off < 256; off <<= 1) {
            __syncthreads();
            double v = dsrc[t]; if (t >= off) v += dsrc[t - off];
            ddst[t] = v;
            double* tmp = dsrc; dsrc = ddst; ddst = tmp;
        }
        __syncthreads();
        g_wbp[o * 256 + t] = dsrc[t];
    } else {
        // ---- transpose x [B,D] -> g_xT [D,B] ----
        float (*tile)[33] = (float(*)[33])raw;
        const int tix = blk - 1280;
        const int d0i = (tix & 15) * 32, b0i = (tix >> 4) * 32;
        const int col = t & 31, rr = t >> 5;
#pragma unroll
        for (int i = 0; i < 4; i++) {
            int row = rr + 8 * i;
            tile[row][col] = x[(b0i + row) * D_ + d0i + col];
        }
        __syncthreads();
#pragma unroll
        for (int i = 0; i < 4; i++) {
            int row = rr + 8 * i;
            g_xT[(d0i + row) * B_ + b0i + col] = tile[col][row];
        }
    }
}

// ============================================================
// kP2: k1 partials only (needs t input) — 512 blocks, IDENTICAL math to R2 k1
// ============================================================
__global__ __launch_bounds__(256) void kP2(const float* __restrict__ x,
                                           const float* __restrict__ tt) {
    __shared__ float xs[32][32];
    __shared__ float ts[32][64];
    const int blk = blockIdx.x;
    const int d0 = (blk & 15) * 32;
    const int o0 = ((blk >> 4) & 3) * 64;
    const int bz = blk >> 6;
    const int b0 = bz * (B_ / NSPLIT);
    const int tid = threadIdx.x;
    const int dg = tid & 15;
    const int og = tid >> 4;

    float acc[2][4];
#pragma unroll
    for (int i = 0; i < 2; i++)
#pragma unroll
        for (int j = 0; j < 4; j++) acc[i][j] = 0.0f;

    for (int bc = 0; bc < B_ / NSPLIT; bc += 32) {
#pragma unroll
        for (int i = tid; i < 32 * 32; i += 256) {
            int bb = i >> 5, dd = i & 31;
            xs[bb][dd] = 1.0f - x[(b0 + bc + bb) * D_ + d0 + dd];
        }
#pragma unroll
        for (int i = tid; i < 32 * 64; i += 256) {
            int bb = i >> 6, oo = i & 63;
            ts[bb][oo] = 1.0f - tt[(b0 + bc + bb) * O_ + o0 + oo];
        }
        __syncthreads();
#pragma unroll 4
        for (int bb = 0; bb < 32; ++bb) {
            float x0 = xs[bb][dg * 2 + 0];
            float x1 = xs[bb][dg * 2 + 1];
            float t0 = ts[bb][og * 4 + 0];
            float t1 = ts[bb][og * 4 + 1];
            float t2 = ts[bb][og * 4 + 2];
            float t3 = ts[bb][og * 4 + 3];
            acc[0][0] += fminf(x0, t0); acc[0][1] += fminf(x0, t1);
            acc[0][2] += fminf(x0, t2); acc[0][3] += fminf(x0, t3);
            acc[1][0] += fminf(x1, t0); acc[1][1] += fminf(x1, t1);
            acc[1][2] += fminf(x1, t2); acc[1][3] += fminf(x1, t3);
        }
        __syncthreads();
    }
    float* outp = g_Mpart + bz * (D_ * O_);
#pragma unroll
    for (int i = 0; i < 2; i++)
#pragma unroll
        for (int j = 0; j < 4; j++)
            outp[(d0 + dg * 2 + i) * O_ + (o0 + og * 4 + j)] = acc[i][j];
}

// ============================================================
// kQ: blocks [0,512) rel_x (=k1b, IDENTICAL) | [512,1536) rel_w via buckets
// ============================================================
__global__ __launch_bounds__(256) void kQ(const float* __restrict__ tt) {
    __shared__ __align__(16) unsigned char raw[8192];
    const int blk = blockIdx.x;
    const int t = threadIdx.x;

    if (blk < 512) {
        int idx = blk * 256 + t;
        int d = idx >> 8;
        float s = 0.0f;
#pragma unroll
        for (int z = 0; z < NSPLIT; z++) s += g_Mpart[z * (D_ * O_) + idx];
        g_relx[idx] = 1.0f - __fdiv_rn(s, g_Sx[d]);
    } else {
        const int q = blk - 512;
        const int o = q & 255;
        const int b = (q >> 8) * 256 + t;
        float*  SV = (float*)raw;            // 512
        int*    BS = (int*)(raw + 2048);     // 257
        double* BP = (double*)(raw + 4096);  // 256
        SV[t] = g_wval[o * D_ + t];
        SV[t + 256] = g_wval[o * D_ + t + 256];
        BS[t] = g_wbs[o * 260 + t];
        if (t == 0) BS[256] = g_wbs[o * 260 + 256];
        BP[t] = g_wbp[o * 256 + t];
        __syncthreads();
        float c = 1.0f - tt[b * O_ + o];
        int k = (int)(c * 256.0f); k = max(0, min(255, k));
        int lo = BS[k], hi = BS[k + 1];
        double S = (k > 0) ? BP[k - 1] : 0.0;
        int ngt = D_ - hi;
        for (int e = lo; e < hi; ++e) {
            float v = SV[e];
            if (v <= c) S += (double)v; else ngt++;
        }
        S += (double)c * (double)ngt;
        float sw = (float)BP[255];
        g_relw[b * O_ + o] = 1.0f - __fdiv_rn((float)S, sw);
    }
}

// ============================================================
// kR: blocks [0,256) per-o bucket + early-exit scan -> out0
//     blocks [256,1280) k4 binary search -> out1
// ============================================================
__global__ __launch_bounds__(256) void kR(const float* __restrict__ x,
                                          const float* __restrict__ w,
                                          float* __restrict__ out) {
    __shared__ __align__(16) unsigned char raw[16384];
    const int blk = blockIdx.x;
    const int t = threadIdx.x;

    if (blk < O_) {
        const int o = blk;
        float* CV = (float*)raw;             // 512: rel_x column
        float* SVa = (float*)(raw + 2048);   // 512: bucket-ordered values
        int*   SI = (int*)(raw + 4096);      // 512: original d
        float* SB = (float*)(raw + 6144);    // 512: per-position bucket min
        int*   KY = (int*)(raw + 8192);      // 512: keys
        int*   H0 = (int*)(raw + 10240);     // 256
        int*   H1 = (int*)(raw + 11264);     // 256
        float* RD = (float*)(raw + 12288);   // 256: min reduce
        float* RX = (float*)(raw + 13312);   // 256: max reduce

        CV[t] = g_relx[t * O_ + o];
        CV[t + 256] = g_relx[(t + 256) * O_ + o];
        __syncthreads();
        RD[t] = fminf(CV[t], CV[t + 256]);
        RX[t] = fmaxf(CV[t], CV[t + 256]);
        __syncthreads();
        for (int k = 128; k > 0; k >>= 1) {
            if (t < k) { RD[t] = fminf(RD[t], RD[t + k]); RX[t] = fmaxf(RX[t], RX[t + k]); }
            __syncthreads();
        }
        const float mn = RD[0];
        const float range = RX[0] - mn;
        const float inv = (range > 0.0f) ? 255.0f / range : 0.0f;
        H0[t] = 0;
        __syncthreads();
        for (int e = t; e < D_; e += 256) {
            int k = (int)((CV[e] - mn) * inv); k = max(0, min(255, k));
            KY[e] = k;
            atomicAdd(&H0[k], 1);
        }
        int* isrc = H0; int* idst = H1;
        for (int off = 1; off < 256; off <<= 1) {
            __syncthreads();
            int v = isrc[t]; if (t >= off) v += isrc[t - off];
            idst[t] = v;
            int* tmp = isrc; isrc = idst; idst = tmp;
        }
        __syncthreads();
        const int excl = (t == 0) ? 0 : isrc[t - 1];
        const int bcnt = isrc[t] - excl;
        idst[t] = excl;
        __syncthreads();
        for (int e = t; e < D_; e += 256) {
            int pos = atomicAdd(&idst[KY[e]], 1);
            SVa[pos] = CV[e];
            SI[pos] = e;
        }
        __syncthreads();
        {   // per-bucket min -> per-position bound
            const int end = idst[t];          // ofs advanced to bucket end
            const int start = end - bcnt;
            float m = CUDART_INF_F;
            for (int p = start; p < end; ++p) m = fminf(m, SVa[p]);
            for (int p = start; p < end; ++p) SB[p] = m;
        }
        __syncthreads();
        // early-exit scan: exact argmin (breaks only at bucket boundaries)
        for (int ch = 0; ch < 4; ++ch) {
            const int b = ch * 256 + t;
            float best = CUDART_INF_F;
            int bestd = 0x7FFFFFFF;
            for (int k = 0; k < D_; ++k) {
                if (SB[k] > best) break;
                float r = SVa[k];
                int d = SI[k];
                float v = fmaxf(g_xT[d * B_ + b], r);
                if (v < best || (v == best && d < bestd)) { best = v; bestd = d; }
            }
            out[b * O_ + o] = fmaxf(g_xT[bestd * B_ + b], w[bestd * O_ + o]);
        }
    } else {
        const int idx = (blk - O_) * 256 + t;
        const int b = idx >> 8;
        const int o = idx & 255;
        const float c = g_relw[idx];
        int lo = 0, hi = D_;
        while (lo < hi) {                     // first d with pm[d] <= c
            int mid = (lo + hi) >> 1;
            if (g_pm[mid * O_ + o] <= c) hi = mid; else lo = mid + 1;
        }
        const int dstar = (lo < D_) ? lo : g_argw[o];
        out[B_ * O_ + idx] = fmaxf(x[b * D_ + dstar], w[dstar * O_ + o]);
    }
}

// ============================================================
extern "C" void kernel_launch(void* const* d_in, const int* in_sizes, int n_in,
                              void* d_out, int out_size) {
    const float* x = (const float*)d_in[0];   // (B, D)
    const float* w = (const float*)d_in[1];   // (D, O)
    const float* t = (const float*)d_in[2];   // (B, O)
    float* out = (float*)d_out;               // [chosen_x (B,O); chosen_w (B,O)]

    kP2<<<512, 256>>>(x, t);                  // k1 partials
    kP<<<1792, 256>>>(x, w);                  // Sx | w-buckets | transpose (k1 range idles)
    kQ<<<1536, 256>>>(t);                     // rel_x | rel_w
    kR<<<1280, 256>>>(x, w, out);             // scan | k4
}

// round 6
// speedup vs baseline: 2.6431x; 1.3436x over previous
#include <cuda_runtime.h>
#include <math_constants.h>

#define B_ 1024
#define D_ 512
#define O_ 256
#define NSPLIT 8

// ---- scratch (no allocations allowed) ----
__device__ float  g_Mpart[NSPLIT * D_ * O_];
__device__ float  g_relx[D_ * O_];
__device__ float  g_relwT[O_ * B_];          // rel_w transposed [o][b]
__device__ float  g_Sx[D_];
__device__ float  g_pmT[O_ * D_];            // prefix-min of w, transposed [o][d]
__device__ int    g_argw[O_];
__device__ float  g_xT[D_ * B_];             // x transposed [d][b]
__device__ float  g_tT[O_ * B_];             // t transposed [o][b]
__device__ float  g_wval[O_ * D_];           // bucket-ordered a'=1-w per o
__device__ int    g_wbs[O_ * 260];           // bucket starts per o
__device__ double g_wbp[O_ * 256];           // fp64 inclusive prefix of bucket sums
__device__ float  g_sva[O_ * D_];            // bucket-ordered rel_x per o
__device__ int    g_si[O_ * D_];             // original d
__device__ float  g_sb[O_ * D_];             // per-position bucket-min bound

// ============================================================
// kA: [0,512) k1 partials | [512,1024) Sx | [1024,1280) w-prep
//     [1280,1792) transpose x | [1792,2048) transpose t
// ============================================================
__global__ __launch_bounds__(256) void kA(const float* __restrict__ x,
                                          const float* __restrict__ w,
                                          const float* __restrict__ tt) {
    __shared__ __align__(16) unsigned char raw[16384];
    __shared__ int s_argw;
    const int blk = blockIdx.x;
    const int t = threadIdx.x;

    if (blk < 512) {
        // ---- k1 partials: IDENTICAL math to R2 k1 ----
        float (*xs)[32] = (float(*)[32])raw;
        float (*ts)[64] = (float(*)[64])(raw + 4096);
        const int d0 = (blk & 15) * 32;
        const int o0 = ((blk >> 4) & 3) * 64;
        const int bz = blk >> 6;
        const int b0 = bz * (B_ / NSPLIT);
        const int dg = t & 15;
        const int og = t >> 4;
        float acc[2][4];
#pragma unroll
        for (int i = 0; i < 2; i++)
#pragma unroll
            for (int j = 0; j < 4; j++) acc[i][j] = 0.0f;
        for (int bc = 0; bc < B_ / NSPLIT; bc += 32) {
#pragma unroll
            for (int i = t; i < 32 * 32; i += 256) {
                int bb = i >> 5, dd = i & 31;
                xs[bb][dd] = 1.0f - x[(b0 + bc + bb) * D_ + d0 + dd];
            }
#pragma unroll
            for (int i = t; i < 32 * 64; i += 256) {
                int bb = i >> 6, oo = i & 63;
                ts[bb][oo] = 1.0f - tt[(b0 + bc + bb) * O_ + o0 + oo];
            }
            __syncthreads();
#pragma unroll 4
            for (int bb = 0; bb < 32; ++bb) {
                float x0 = xs[bb][dg * 2 + 0];
                float x1 = xs[bb][dg * 2 + 1];
                float t0 = ts[bb][og * 4 + 0];
                float t1 = ts[bb][og * 4 + 1];
                float t2 = ts[bb][og * 4 + 2];
                float t3 = ts[bb][og * 4 + 3];
                acc[0][0] += fminf(x0, t0); acc[0][1] += fminf(x0, t1);
                acc[0][2] += fminf(x0, t2); acc[0][3] += fminf(x0, t3);
                acc[1][0] += fminf(x1, t0); acc[1][1] += fminf(x1, t1);
                acc[1][2] += fminf(x1, t2); acc[1][3] += fminf(x1, t3);
            }
            __syncthreads();
        }
        float* outp = g_Mpart + bz * (D_ * O_);
#pragma unroll
        for (int i = 0; i < 2; i++)
#pragma unroll
            for (int j = 0; j < 4; j++)
                outp[(d0 + dg * 2 + i) * O_ + (o0 + og * 4 + j)] = acc[i][j];
    } else if (blk < 1024) {
        // ---- Sx[d] (identical to R2) ----
        float* sm = (float*)raw;
        int d = blk - 512;
        float s = 0.0f;
        for (int b = t; b < B_; b += 256) s += (1.0f - x[b * D_ + d]);
        sm[t] = s; __syncthreads();
        for (int k = 128; k > 0; k >>= 1) {
            if (t < k) sm[t] += sm[t + k];
            __syncthreads();
        }
        if (t == 0) g_Sx[d] = sm[0];
    } else if (blk < 1280) {
        // ---- per-o: prefix-min -> pmT, argw, bucket (1-w), fp64 prefix ----
        const int o = blk - 1024;
        float*  F0 = (float*)raw;
        float*  F1 = (float*)(raw + 2048);
        float*  F2 = (float*)(raw + 4096);
        int*    KY = (int*)(raw + 6144);
        int*    H0 = (int*)(raw + 8192);
        int*    H1 = (int*)(raw + 9216);
        double* P0 = (double*)(raw + 10240);
        double* P1 = (double*)(raw + 12288);

        F0[t] = w[t * O_ + o];
        F0[t + 256] = w[(t + 256) * O_ + o];
        if (t == 0) s_argw = 0x7FFFFFFF;
        F1[t] = F0[t]; F1[t + 256] = F0[t + 256];
        {
            float* src = F1; float* dst = F2;
            for (int off = 1; off < D_; off <<= 1) {
                __syncthreads();
                for (int e = t; e < D_; e += 256) {
                    float v = src[e];
                    if (e >= off) v = fminf(v, src[e - off]);
                    dst[e] = v;
                }
                float* tmp = src; src = dst; dst = tmp;
            }
            __syncthreads();
            for (int e = t; e < D_; e += 256) g_pmT[o * D_ + e] = src[e];
            float wmin = src[D_ - 1];
            __syncthreads();
            for (int e = t; e < D_; e += 256)
                if (F0[e] == wmin) atomicMin(&s_argw, e);
        }
        H0[t] = 0;
        __syncthreads();
        for (int e = t; e < D_; e += 256) {
            float a = 1.0f - F0[e];
            int k = (int)(a * 256.0f); k = max(0, min(255, k));
            KY[e] = k;
            atomicAdd(&H0[k], 1);
        }
        __syncthreads();
        if (t == 0) g_argw[o] = s_argw;
        int* isrc = H0; int* idst = H1;
        for (int off = 1; off < 256; off <<= 1) {
            __syncthreads();
            int v = isrc[t]; if (t >= off) v += isrc[t - off];
            idst[t] = v;
            int* tmp = isrc; isrc = idst; idst = tmp;
        }
        __syncthreads();
        int excl = (t == 0) ? 0 : isrc[t - 1];
        g_wbs[o * 260 + t] = excl;
        if (t == 255) g_wbs[o * 260 + 256] = D_;
        idst[t] = excl;
        P0[t] = 0.0;
        __syncthreads();
        for (int e = t; e < D_; e += 256) {
            float a = 1.0f - F0[e];
            int k = KY[e];
            int pos = atomicAdd(&idst[k], 1);
            g_wval[o * D_ + pos] = a;
            atomicAdd(&P0[k], (double)a);
        }
        double* dsrc = P0; double* ddst = P1;
        for (int off = 1; off < 256; off <<= 1) {
            __syncthreads();
            double v = dsrc[t]; if (t >= off) v += dsrc[t - off];
            ddst[t] = v;
            double* tmp = dsrc; dsrc = ddst; ddst = tmp;
        }
        __syncthreads();
        g_wbp[o * 256 + t] = dsrc[t];
    } else if (blk < 1792) {
        // ---- transpose x -> g_xT ----
        float (*tile)[33] = (float(*)[33])raw;
        const int tix = blk - 1280;
        const int d0i = (tix & 15) * 32, b0i = (tix >> 4) * 32;
        const int col = t & 31, rr = t >> 5;
#pragma unroll
        for (int i = 0; i < 4; i++) {
            int row = rr + 8 * i;
            tile[row][col] = x[(b0i + row) * D_ + d0i + col];
        }
        __syncthreads();
#pragma unroll
        for (int i = 0; i < 4; i++) {
            int row = rr + 8 * i;
            g_xT[(d0i + row) * B_ + b0i + col] = tile[col][row];
        }
    } else {
        // ---- transpose t -> g_tT  (B x O -> O x B) ----
        float (*tile)[33] = (float(*)[33])raw;
        const int tix = blk - 1792;          // 256 tiles: 32 (b) x 8 (o)
        const int o0i = (tix & 7) * 32, b0i = (tix >> 3) * 32;
        const int col = t & 31, rr = t >> 5;
#pragma unroll
        for (int i = 0; i < 4; i++) {
            int row = rr + 8 * i;
            tile[row][col] = tt[(b0i + row) * O_ + o0i + col];
        }
        __syncthreads();
#pragma unroll
        for (int i = 0; i < 4; i++) {
            int row = rr + 8 * i;
            g_tT[(o0i + row) * B_ + b0i + col] = tile[col][row];
        }
    }
}

// ============================================================
// kB: [0,512) rel_x combine (IDENTICAL) | [512,1536) rel_w via buckets
// ============================================================
__global__ __launch_bounds__(256) void kB() {
    __shared__ __align__(16) unsigned char raw[8192];
    const int blk = blockIdx.x;
    const int t = threadIdx.x;

    if (blk < 512) {
        int idx = blk * 256 + t;
        int d = idx >> 8;
        float s = 0.0f;
#pragma unroll
        for (int z = 0; z < NSPLIT; z++) s += g_Mpart[z * (D_ * O_) + idx];
        g_relx[idx] = 1.0f - __fdiv_rn(s, g_Sx[d]);
    } else {
        const int q = blk - 512;
        const int o = q & 255;
        const int b = (q >> 8) * 256 + t;
        float*  SV = (float*)raw;
        int*    BS = (int*)(raw + 2048);
        double* BP = (double*)(raw + 4096);
        SV[t] = g_wval[o * D_ + t];
        SV[t + 256] = g_wval[o * D_ + t + 256];
        BS[t] = g_wbs[o * 260 + t];
        if (t == 0) BS[256] = g_wbs[o * 260 + 256];
        BP[t] = g_wbp[o * 256 + t];
        __syncthreads();
        float c = 1.0f - g_tT[o * B_ + b];
        int k = (int)(c * 256.0f); k = max(0, min(255, k));
        int lo = BS[k], hi = BS[k + 1];
        double S = (k > 0) ? BP[k - 1] : 0.0;
        int ngt = D_ - hi;
        for (int e = lo; e < hi; ++e) {
            float v = SV[e];
            if (v <= c) S += (double)v; else ngt++;
        }
        S += (double)c * (double)ngt;
        float sw = (float)BP[255];
        g_relwT[o * B_ + b] = 1.0f - __fdiv_rn((float)S, sw);
    }
}

// ============================================================
// kC: [0,256) rel_x bucket-build per o -> g_sva/g_si/g_sb
//     [256,1280) k4: smem binary search on pmT -> out1
// ============================================================
__global__ __launch_bounds__(256) void kC(const float* __restrict__ x,
                                          const float* __restrict__ w,
                                          float* __restrict__ out) {
    __shared__ __align__(16) unsigned char raw[16384];
    const int blk = blockIdx.x;
    const int t = threadIdx.x;

    if (blk < O_) {
        const int o = blk;
        float* CV  = (float*)raw;             // 512
        float* SVa = (float*)(raw + 2048);    // 512
        int*   SI  = (int*)(raw + 4096);      // 512
        float* SB  = (float*)(raw + 6144);    // 512
        int*   KY  = (int*)(raw + 8192);      // 512
        int*   H0  = (int*)(raw + 10240);     // 256
        int*   H1  = (int*)(raw + 11264);     // 256
        float* RD  = (float*)(raw + 12288);   // 256
        float* RX  = (float*)(raw + 13312);   // 256

        CV[t] = g_relx[t * O_ + o];
        CV[t + 256] = g_relx[(t + 256) * O_ + o];
        __syncthreads();
        RD[t] = fminf(CV[t], CV[t + 256]);
        RX[t] = fmaxf(CV[t], CV[t + 256]);
        __syncthreads();
        for (int k = 128; k > 0; k >>= 1) {
            if (t < k) { RD[t] = fminf(RD[t], RD[t + k]); RX[t] = fmaxf(RX[t], RX[t + k]); }
            __syncthreads();
        }
        const float mn = RD[0];
        const float range = RX[0] - mn;
        const float inv = (range > 0.0f) ? 255.0f / range : 0.0f;
        H0[t] = 0;
        __syncthreads();
        for (int e = t; e < D_; e += 256) {
            int k = (int)((CV[e] - mn) * inv); k = max(0, min(255, k));
            KY[e] = k;
            atomicAdd(&H0[k], 1);
        }
        int* isrc = H0; int* idst = H1;
        for (int off = 1; off < 256; off <<= 1) {
            __syncthreads();
            int v = isrc[t]; if (t >= off) v += isrc[t - off];
            idst[t] = v;
            int* tmp = isrc; isrc = idst; idst = tmp;
        }
        __syncthreads();
        const int excl = (t == 0) ? 0 : isrc[t - 1];
        const int bcnt = isrc[t] - excl;
        idst[t] = excl;
        __syncthreads();
        for (int e = t; e < D_; e += 256) {
            int pos = atomicAdd(&idst[KY[e]], 1);
            SVa[pos] = CV[e];
            SI[pos] = e;
        }
        __syncthreads();
        {
            const int end = idst[t];
            const int start = end - bcnt;
            float m = CUDART_INF_F;
            for (int p = start; p < end; ++p) m = fminf(m, SVa[p]);
            for (int p = start; p < end; ++p) SB[p] = m;
        }
        __syncthreads();
        g_sva[o * D_ + t] = SVa[t];      g_sva[o * D_ + t + 256] = SVa[t + 256];
        g_si [o * D_ + t] = SI[t];       g_si [o * D_ + t + 256] = SI[t + 256];
        g_sb [o * D_ + t] = SB[t];       g_sb [o * D_ + t + 256] = SB[t + 256];
    } else {
        // ---- k4: block (o fixed, 256 b's), pm column in smem ----
        const int q = blk - O_;
        const int o = q & 255;
        const int b = (q >> 8) * 256 + t;
        float* PM = (float*)raw;              // 512
        PM[t] = g_pmT[o * D_ + t];
        PM[t + 256] = g_pmT[o * D_ + t + 256];
        __syncthreads();
        const float c = g_relwT[o * B_ + b];
        int lo = 0, hi = D_;
        while (lo < hi) {                     // first d with pm[d] <= c
            int mid = (lo + hi) >> 1;
            if (PM[mid] <= c) hi = mid; else lo = mid + 1;
        }
        const int dstar = (lo < D_) ? lo : g_argw[o];
        out[B_ * O_ + b * O_ + o] = fmaxf(x[b * D_ + dstar], w[dstar * O_ + o]);
    }
}

// ============================================================
// kD: k3 scan, 1024 blocks = (o, b-chunk); chunk-of-8 prefetch, exact early exit
// ============================================================
__global__ __launch_bounds__(256) void kD(const float* __restrict__ w,
                                          float* __restrict__ out) {
    __shared__ float SVa[512];
    __shared__ int   SI[512];
    __shared__ float SB[512];
    const int blk = blockIdx.x;
    const int t = threadIdx.x;
    const int o = blk & 255;
    const int b = (blk >> 8) * 256 + t;

    SVa[t] = g_sva[o * D_ + t];  SVa[t + 256] = g_sva[o * D_ + t + 256];
    SI[t]  = g_si[o * D_ + t];   SI[t + 256]  = g_si[o * D_ + t + 256];
    SB[t]  = g_sb[o * D_ + t];   SB[t + 256]  = g_sb[o * D_ + t + 256];
    __syncthreads();

    float best = CUDART_INF_F;
    int bestd = 0x7FFFFFFF;
    for (int ch = 0; ch < D_; ch += 8) {
        if (SB[ch] > best) break;             // exact: SB non-decreasing
        float xv[8];
        int dd[8];
#pragma unroll
        for (int i = 0; i < 8; i++) {
            dd[i] = SI[ch + i];
            xv[i] = g_xT[dd[i] * B_ + b];     // 8 independent coalesced loads
        }
#pragma unroll
        for (int i = 0; i < 8; i++) {
            float v = fmaxf(xv[i], SVa[ch + i]);
            if (v < best || (v == best && dd[i] < bestd)) { best = v; bestd = dd[i]; }
        }
    }
    out[b * O_ + o] = fmaxf(g_xT[bestd * B_ + b], w[bestd * O_ + o]);
}

// ============================================================
extern "C" void kernel_launch(void* const* d_in, const int* in_sizes, int n_in,
                              void* d_out, int out_size) {
    const float* x = (const float*)d_in[0];   // (B, D)
    const float* w = (const float*)d_in[1];   // (D, O)
    const float* t = (const float*)d_in[2];   // (B, O)
    float* out = (float*)d_out;

    kA<<<2048, 256>>>(x, w, t);
    kB<<<1536, 256>>>();
    kC<<<1280, 256>>>(x, w, out);
    kD<<<1024, 256>>>(w, out);
}